// round 5
// baseline (speedup 1.0000x reference)
#include <cuda_runtime.h>
#include <cuda_bf16.h>
#include <math.h>

#define N_NODES   50000
#define N_EDGES   800000
#define E_TOT     (N_EDGES + N_NODES)
#define D_IN      128
#define HEADS     8
#define CDIM      32
#define HIDDEN    256
#define NEG_SLOPE 0.2f
#define FULLM     0xffffffffu

// ---------------- device scratch (zero-initialized at module load) ------------------
__device__ __align__(128) __nv_bfloat16 g_hb[N_NODES * HIDDEN];  // 25.6 MB
__device__ __align__(128) float g_asrc [N_NODES * HEADS];
__device__ __align__(128) float g_adst [N_NODES * HEADS];
__device__ __align__(128) float g_pooled[HIDDEN];        // zeroed by k_mlp after read
__device__ __align__(128) int   g_hist [N_NODES];        // zeroed by k_scan after read
__device__ __align__(128) int   g_ptr  [N_NODES + 1];
__device__ __align__(128) int   g_cur  [N_NODES];
__device__ __align__(128) int   g_csr_src[E_TOT];

__device__ __forceinline__ void red_add_v4(float* addr, float a, float b, float c, float d) {
    asm volatile("red.global.add.v4.f32 [%0], {%1,%2,%3,%4};"
                 :: "l"(addr), "f"(a), "f"(b), "f"(c), "f"(d) : "memory");
}
__device__ __forceinline__ unsigned long long pack_f32x2(float lo, float hi) {
    unsigned long long r;
    asm("mov.b64 %0, {%1,%2};" : "=l"(r) : "f"(lo), "f"(hi));
    return r;
}
__device__ __forceinline__ void unpack_f32x2(float& lo, float& hi, unsigned long long v) {
    asm("mov.b64 {%0,%1}, %2;" : "=f"(lo), "=f"(hi) : "l"(v));
}

// ---------------- K1: in-degree histogram -------------------------------------------
__global__ __launch_bounds__(256) void k_hist(const int* __restrict__ ei) {
    int e = blockIdx.x * 256 + threadIdx.x;
    if (e >= E_TOT) return;
    int d = (e < N_EDGES) ? ei[N_EDGES + e] : (e - N_EDGES);
    atomicAdd(&g_hist[d], 1);
}

// ---------------- K2: single-block scan (self-restores g_hist to 0) -----------------
#define SCAN_T 1024
__global__ __launch_bounds__(SCAN_T) void k_scan() {
    __shared__ int sm[SCAN_T];
    const int t = threadIdx.x;
    const int chunk = (N_NODES + SCAN_T - 1) / SCAN_T;
    const int beg = t * chunk;
    int sum = 0;
    for (int i = 0; i < chunk; i++) {
        int idx = beg + i;
        if (idx < N_NODES) sum += g_hist[idx];
    }
    sm[t] = sum;
    __syncthreads();
    for (int ofs = 1; ofs < SCAN_T; ofs <<= 1) {
        int v = (t >= ofs) ? sm[t - ofs] : 0;
        __syncthreads();
        sm[t] += v;
        __syncthreads();
    }
    int run = sm[t] - sum;
    for (int i = 0; i < chunk; i++) {
        int idx = beg + i;
        if (idx < N_NODES) {
            int c = g_hist[idx];
            g_ptr[idx] = run;
            g_cur[idx] = run;
            run += c;
            g_hist[idx] = 0;    // restore invariant for next replay
        }
    }
    if (t == SCAN_T - 1) g_ptr[N_NODES] = E_TOT;
}

// ---------------- K3: scatter edges into CSR ----------------------------------------
__global__ __launch_bounds__(256) void k_scatter(const int* __restrict__ ei) {
    int e = blockIdx.x * 256 + threadIdx.x;
    if (e >= E_TOT) return;
    int s, d;
    if (e < N_EDGES) { s = ei[e]; d = ei[N_EDGES + e]; }
    else             { s = d = e - N_EDGES; }
    int pos = atomicAdd(&g_cur[d], 1);
    g_csr_src[pos] = s;
}

// ---------------- K4: h = x @ W  (f32x2 packed FMA, 128x128 tile, 8x8 micro) --------
#define BM 128
#define BN 128
#define BK 16
#define XS_STRIDE 132
#define WS_STRIDE 132

__global__ __launch_bounds__(256) void k_gemm(const float* __restrict__ x,
                                              const float* __restrict__ W) {
    __shared__ __align__(16) float xs[BK * XS_STRIDE];  // [k][m]
    __shared__ __align__(16) float ws[BK * WS_STRIDE];  // [k][n]
    const int t     = threadIdx.x;
    const int mBase = blockIdx.x * BM;
    const int nBase = blockIdx.y * BN;
    const int tx    = t & 15;   // 8 cols each
    const int ty    = t >> 4;   // 8 rows each

    unsigned long long acc[8][4];   // col pairs
#pragma unroll
    for (int i = 0; i < 8; i++)
#pragma unroll
        for (int j = 0; j < 4; j++) acc[i][j] = 0ull;

    for (int kBase = 0; kBase < D_IN; kBase += BK) {
#pragma unroll
        for (int p = 0; p < 2; p++) {
            int id   = t + p * 256;
            int row  = id >> 2;
            int quad = id & 3;
            int m    = mBase + row;
            float4 v = make_float4(0.f, 0.f, 0.f, 0.f);
            if (m < N_NODES)
                v = *(const float4*)(x + (size_t)m * D_IN + kBase + quad * 4);
            int k = quad * 4;
            xs[(k + 0) * XS_STRIDE + row] = v.x;
            xs[(k + 1) * XS_STRIDE + row] = v.y;
            xs[(k + 2) * XS_STRIDE + row] = v.z;
            xs[(k + 3) * XS_STRIDE + row] = v.w;
        }
#pragma unroll
        for (int p = 0; p < 2; p++) {
            int id = t + p * 256;
            int kr = id >> 5;
            int c  = (id & 31) * 4;
            float4 v = *(const float4*)(W + (size_t)(kBase + kr) * HIDDEN + nBase + c);
            *(float4*)(ws + kr * WS_STRIDE + c) = v;
        }
        __syncthreads();

#pragma unroll
        for (int kk = 0; kk < BK; kk++) {
            float4 x0 = *(const float4*)(xs + kk * XS_STRIDE + ty * 8);
            float4 x1 = *(const float4*)(xs + kk * XS_STRIDE + ty * 8 + 4);
            // W col pairs as 64-bit values (16B-aligned)
            const unsigned long long* wq =
                (const unsigned long long*)(ws + kk * WS_STRIDE + tx * 8);
            unsigned long long w0 = wq[0], w1 = wq[1], w2 = wq[2], w3 = wq[3];
            float xr[8] = {x0.x, x0.y, x0.z, x0.w, x1.x, x1.y, x1.z, x1.w};
#pragma unroll
            for (int i = 0; i < 8; i++) {
                unsigned long long xp = pack_f32x2(xr[i], xr[i]);
                asm("fma.rn.f32x2 %0, %1, %2, %0;" : "+l"(acc[i][0]) : "l"(xp), "l"(w0));
                asm("fma.rn.f32x2 %0, %1, %2, %0;" : "+l"(acc[i][1]) : "l"(xp), "l"(w1));
                asm("fma.rn.f32x2 %0, %1, %2, %0;" : "+l"(acc[i][2]) : "l"(xp), "l"(w2));
                asm("fma.rn.f32x2 %0, %1, %2, %0;" : "+l"(acc[i][3]) : "l"(xp), "l"(w3));
            }
        }
        __syncthreads();
    }

#pragma unroll
    for (int i = 0; i < 8; i++) {
        int m = mBase + ty * 8 + i;
        if (m < N_NODES) {
            float a0, a1, a2, a3, a4, a5, a6, a7;
            unpack_f32x2(a0, a1, acc[i][0]);
            unpack_f32x2(a2, a3, acc[i][1]);
            unpack_f32x2(a4, a5, acc[i][2]);
            unpack_f32x2(a6, a7, acc[i][3]);
            __nv_bfloat162 b0 = __floats2bfloat162_rn(a0, a1);
            __nv_bfloat162 b1 = __floats2bfloat162_rn(a2, a3);
            __nv_bfloat162 b2 = __floats2bfloat162_rn(a4, a5);
            __nv_bfloat162 b3 = __floats2bfloat162_rn(a6, a7);
            uint4 pack;
            pack.x = *(unsigned*)&b0; pack.y = *(unsigned*)&b1;
            pack.z = *(unsigned*)&b2; pack.w = *(unsigned*)&b3;
            *(uint4*)(g_hb + (size_t)m * HIDDEN + nBase + tx * 8) = pack;
        }
    }
}

// ---------------- K5: per-node attention logits (bf16 h) ----------------------------
__global__ __launch_bounds__(256) void k_att(const float* __restrict__ att_src,
                                             const float* __restrict__ att_dst) {
    int idx = blockIdx.x * 256 + threadIdx.x;
    if (idx >= N_NODES * HEADS) return;
    int n = idx >> 3, hd = idx & 7;
    const __nv_bfloat162* hp = (const __nv_bfloat162*)(g_hb + (size_t)n * HIDDEN + hd * CDIM);
    const float* ap = att_src + hd * CDIM;
    const float* bp = att_dst + hd * CDIM;
    float ss = 0.f, sd = 0.f;
#pragma unroll
    for (int i = 0; i < 16; i++) {
        float2 hv = __bfloat1622float2(hp[i]);
        ss += hv.x * ap[2 * i] + hv.y * ap[2 * i + 1];
        sd += hv.x * bp[2 * i] + hv.y * bp[2 * i + 1];
    }
    g_asrc[idx] = ss;
    g_adst[idx] = sd;
}

// ---------------- K6: warp-per-node aggregation, 4-edge-parallel exp ----------------
// Lane layout (FMA phase): lane owns cols [8*lane, 8*lane+8) -> all in head lane>>2.
// Lane layout (exp phase):  lane = (edge_slot = lane>>3) x (head = lane&7).
#define AGGR_BLOCKS 1184
__global__ __launch_bounds__(256) void k_aggr(const float* __restrict__ bias) {
    const int lane   = threadIdx.x & 31;
    const int warpId = threadIdx.x >> 5;
    const int gw     = blockIdx.x * 8 + warpId;
    const int nWarps = AGGR_BLOCKS * 8;
    const int headA  = lane & 7;     // exp-phase head
    const int sub    = lane >> 3;    // exp-phase edge slot
    const int headC  = lane >> 2;    // fma-phase head (cols 8*lane..)

    float2 bl[4];
    float  pool[8];
#pragma unroll
    for (int j = 0; j < 4; j++) {
        bl[j] = *(const float2*)(bias + 8 * lane + 2 * j);
        pool[2 * j] = 0.f; pool[2 * j + 1] = 0.f;
    }

    for (int n = gw; n < N_NODES; n += nWarps) {
        const int beg = g_ptr[n];
        const int end = g_ptr[n + 1];
        float adst8 = (lane < 8) ? g_adst[n * 8 + lane] : 0.f;
        const float adst = __shfl_sync(FULLM, adst8, headA);

        unsigned long long acc[4];
#pragma unroll
        for (int j = 0; j < 4; j++) acc[j] = 0ull;
        float tsum = 0.f;

        for (int base = beg; base < end; base += 32) {
            const int cnt = min(32, end - base);
            int sv = (base + lane < end) ? g_csr_src[base + lane] : 0;
            const int ngroups = (cnt + 3) >> 2;
            for (int g = 0; g < ngroups; g++) {
                const int g4 = g * 4;
                // --- parallel exp for 4 edges x 8 heads ---
                int se = __shfl_sync(FULLM, sv, g4 + sub);
                float tv = 0.f;
                if (g4 + sub < cnt) {
                    float v = g_asrc[se * 8 + headA] + adst;
                    v = (v > 0.f) ? v : NEG_SLOPE * v;
                    tv = __expf(v);
                }
                tsum += tv;
                // --- gather + FMA for each valid edge ---
                const int ecnt = min(4, cnt - g4);
                for (int ee = 0; ee < ecnt; ee++) {
                    int s = __shfl_sync(FULLM, sv, g4 + ee);
                    float aj = __shfl_sync(FULLM, tv, ee * 8 + headC);
                    unsigned long long ajp = pack_f32x2(aj, aj);
                    uint4 hv = *(const uint4*)(g_hb + (size_t)s * HIDDEN + lane * 8);
#pragma unroll
                    for (int jp = 0; jp < 4; jp++) {
                        unsigned u  = (&hv.x)[jp];
                        unsigned lo = u << 16;
                        unsigned hi = u & 0xFFFF0000u;
                        unsigned long long hp;
                        asm("mov.b64 %0, {%1,%2};" : "=l"(hp) : "r"(lo), "r"(hi));
                        asm("fma.rn.f32x2 %0, %1, %2, %0;"
                            : "+l"(acc[jp]) : "l"(ajp), "l"(hp));
                    }
                }
            }
        }
        // reduce per-head exp sums across the 4 edge slots
        tsum += __shfl_xor_sync(FULLM, tsum, 8);
        tsum += __shfl_xor_sync(FULLM, tsum, 16);
        const float denom = __shfl_sync(FULLM, tsum, headC);
        const float inv = 1.0f / (denom + 1e-16f);
#pragma unroll
        for (int jp = 0; jp < 4; jp++) {
            float ax, ay;
            unpack_f32x2(ax, ay, acc[jp]);
            float ox = fmaf(ax, inv, bl[jp].x);
            float oy = fmaf(ay, inv, bl[jp].y);
            ox = (ox > 0.f) ? ox : (__expf(ox) - 1.0f);
            oy = (oy > 0.f) ? oy : (__expf(oy) - 1.0f);
            pool[2 * jp]     += ox;
            pool[2 * jp + 1] += oy;
        }
    }
    red_add_v4(g_pooled + 8 * lane,     pool[0], pool[1], pool[2], pool[3]);
    red_add_v4(g_pooled + 8 * lane + 4, pool[4], pool[5], pool[6], pool[7]);
}

// ---------------- K7: MLP head (self-restores g_pooled to 0) ------------------------
__global__ __launch_bounds__(256) void k_mlp(const float* __restrict__ W1,
                                             const float* __restrict__ b1,
                                             const float* __restrict__ W2,
                                             const float* __restrict__ b2,
                                             float* __restrict__ out) {
    __shared__ float pm[HIDDEN];
    __shared__ float z[HIDDEN / 2];
    int t = threadIdx.x;
    pm[t] = g_pooled[t] * (1.0f / (float)N_NODES);
    g_pooled[t] = 0.f;    // restore invariant for next replay
    __syncthreads();
    if (t < HIDDEN / 2) {
        float s = b1[t];
#pragma unroll 8
        for (int k = 0; k < HIDDEN; k++) s = fmaf(pm[k], W1[k * (HIDDEN / 2) + t], s);
        z[t] = fmaxf(s, 0.f);
    }
    __syncthreads();
    if (t < 6) {
        float s = b2[t];
#pragma unroll 8
        for (int j = 0; j < HIDDEN / 2; j++) s = fmaf(z[j], W2[j * 6 + t], s);
        out[t] = s;
    }
}

// ---------------- launch -----------------------------------------------------------
extern "C" void kernel_launch(void* const* d_in, const int* in_sizes, int n_in,
                              void* d_out, int out_size) {
    const float* x       = (const float*)d_in[0];
    const int*   ei      = (const int*)  d_in[1];
    const float* W       = (const float*)d_in[2];
    const float* att_src = (const float*)d_in[3];
    const float* att_dst = (const float*)d_in[4];
    const float* bias    = (const float*)d_in[5];
    const float* W1      = (const float*)d_in[6];
    const float* b1      = (const float*)d_in[7];
    const float* W2      = (const float*)d_in[8];
    const float* b2      = (const float*)d_in[9];
    float* out = (float*)d_out;

    // CSR build first (independent of GEMM) so the profiler slot lands on k_gemm
    k_hist<<<(E_TOT + 255) / 256, 256>>>(ei);
    k_scan<<<1, SCAN_T>>>();
    k_scatter<<<(E_TOT + 255) / 256, 256>>>(ei);

    dim3 g1((N_NODES + BM - 1) / BM, HIDDEN / BN);
    k_gemm<<<g1, 256>>>(x, W);

    k_att<<<(N_NODES * HEADS + 255) / 256, 256>>>(att_src, att_dst);

    k_aggr<<<AGGR_BLOCKS, 256>>>(bias);

    k_mlp<<<1, 256>>>(W1, b1, W2, b2, out);
}

// round 6
// speedup vs baseline: 1.2576x; 1.2576x over previous
#include <cuda_runtime.h>
#include <cuda_bf16.h>
#include <math.h>

#define N_NODES   50000
#define N_EDGES   800000
#define E_TOT     (N_EDGES + N_NODES)
#define D_IN      128
#define HEADS     8
#define CDIM      32
#define HIDDEN    256
#define NEG_SLOPE 0.2f
#define FULLM     0xffffffffu

// ---------------- device scratch (zero-initialized at module load) ------------------
__device__ __align__(128) __nv_bfloat16 g_hb[N_NODES * HIDDEN];  // 25.6 MB
__device__ __align__(128) float g_asrc [N_NODES * HEADS];
__device__ __align__(128) float g_adst [N_NODES * HEADS];
__device__ __align__(128) float g_pooled[HIDDEN];        // zeroed by k_mlp after read
__device__ __align__(128) int   g_hist [N_NODES];        // zeroed by k_scan1 after read
__device__ __align__(128) int   g_ptr  [N_NODES + 1];
__device__ __align__(128) int   g_cur  [N_NODES];
__device__ __align__(128) int   g_csr_src[E_TOT];
__device__ __align__(128) int   g_bsum [64];
__device__ __align__(128) int   g_bofs [64];

__device__ __forceinline__ void red_add_v4(float* addr, float a, float b, float c, float d) {
    asm volatile("red.global.add.v4.f32 [%0], {%1,%2,%3,%4};"
                 :: "l"(addr), "f"(a), "f"(b), "f"(c), "f"(d) : "memory");
}
__device__ __forceinline__ unsigned long long pack_f32x2(float lo, float hi) {
    unsigned long long r;
    asm("mov.b64 %0, {%1,%2};" : "=l"(r) : "f"(lo), "f"(hi));
    return r;
}
__device__ __forceinline__ void unpack_f32x2(float& lo, float& hi, unsigned long long v) {
    asm("mov.b64 {%0,%1}, %2;" : "=f"(lo), "=f"(hi) : "l"(v));
}

// ---------------- K: in-degree histogram --------------------------------------------
__global__ __launch_bounds__(256) void k_hist(const int* __restrict__ ei) {
    int e = blockIdx.x * 256 + threadIdx.x;
    if (e >= E_TOT) return;
    int d = (e < N_EDGES) ? ei[N_EDGES + e] : (e - N_EDGES);
    atomicAdd(&g_hist[d], 1);
}

// ---------------- K: scan stage 1 — 50 blocks, block-local exclusive scan -----------
#define NODES_PER_BLK 1000
__global__ __launch_bounds__(1024) void k_scan1() {
    __shared__ int sm[1024];
    const int t = threadIdx.x;
    const int b = blockIdx.x;
    const int idx = b * NODES_PER_BLK + t;
    int c = 0;
    if (t < NODES_PER_BLK) {
        c = g_hist[idx];
        g_hist[idx] = 0;           // restore invariant for next replay
    }
    sm[t] = c;
    __syncthreads();
    for (int ofs = 1; ofs < 1024; ofs <<= 1) {
        int v = (t >= ofs) ? sm[t - ofs] : 0;
        __syncthreads();
        sm[t] += v;
        __syncthreads();
    }
    if (t < NODES_PER_BLK) g_ptr[idx] = sm[t] - c;   // block-local exclusive
    if (t == 1023) g_bsum[b] = sm[1023];
}

// ---------------- K: scan stage 2 — scan the 50 block sums --------------------------
__global__ __launch_bounds__(64) void k_scan2() {
    __shared__ int sm[64];
    const int t = threadIdx.x;
    int c = (t < 50) ? g_bsum[t] : 0;
    sm[t] = c;
    __syncthreads();
    for (int ofs = 1; ofs < 64; ofs <<= 1) {
        int v = (t >= ofs) ? sm[t - ofs] : 0;
        __syncthreads();
        sm[t] += v;
        __syncthreads();
    }
    if (t < 50) g_bofs[t] = sm[t] - c;
    if (t == 0) g_ptr[N_NODES] = E_TOT;
}

// ---------------- K: scan stage 3 — apply block offsets -----------------------------
__global__ __launch_bounds__(1024) void k_scan3() {
    const int t = threadIdx.x;
    const int b = blockIdx.x;
    if (t >= NODES_PER_BLK) return;
    const int idx = b * NODES_PER_BLK + t;
    int v = g_ptr[idx] + g_bofs[b];
    g_ptr[idx] = v;
    g_cur[idx] = v;
}

// ---------------- K: scatter edges into CSR -----------------------------------------
__global__ __launch_bounds__(256) void k_scatter(const int* __restrict__ ei) {
    int e = blockIdx.x * 256 + threadIdx.x;
    if (e >= E_TOT) return;
    int s, d;
    if (e < N_EDGES) { s = ei[e]; d = ei[N_EDGES + e]; }
    else             { s = d = e - N_EDGES; }
    int pos = atomicAdd(&g_cur[d], 1);
    g_csr_src[pos] = s;
}

// ---------------- K: h = x @ W  (f32x2 packed FMA, 128x128 tile, 8x8 micro) ---------
#define BM 128
#define BN 128
#define BK 16
#define XS_STRIDE 132
#define WS_STRIDE 132

__global__ __launch_bounds__(256) void k_gemm(const float* __restrict__ x,
                                              const float* __restrict__ W) {
    __shared__ __align__(16) float xs[BK * XS_STRIDE];  // [k][m]
    __shared__ __align__(16) float ws[BK * WS_STRIDE];  // [k][n]
    const int t     = threadIdx.x;
    const int mBase = blockIdx.x * BM;
    const int nBase = blockIdx.y * BN;
    const int tx    = t & 15;   // 8 cols each
    const int ty    = t >> 4;   // 8 rows each

    unsigned long long acc[8][4];   // col pairs
#pragma unroll
    for (int i = 0; i < 8; i++)
#pragma unroll
        for (int j = 0; j < 4; j++) acc[i][j] = 0ull;

    for (int kBase = 0; kBase < D_IN; kBase += BK) {
#pragma unroll
        for (int p = 0; p < 2; p++) {
            int id   = t + p * 256;
            int row  = id >> 2;
            int quad = id & 3;
            int m    = mBase + row;
            float4 v = make_float4(0.f, 0.f, 0.f, 0.f);
            if (m < N_NODES)
                v = *(const float4*)(x + (size_t)m * D_IN + kBase + quad * 4);
            int k = quad * 4;
            xs[(k + 0) * XS_STRIDE + row] = v.x;
            xs[(k + 1) * XS_STRIDE + row] = v.y;
            xs[(k + 2) * XS_STRIDE + row] = v.z;
            xs[(k + 3) * XS_STRIDE + row] = v.w;
        }
#pragma unroll
        for (int p = 0; p < 2; p++) {
            int id = t + p * 256;
            int kr = id >> 5;
            int c  = (id & 31) * 4;
            float4 v = *(const float4*)(W + (size_t)(kBase + kr) * HIDDEN + nBase + c);
            *(float4*)(ws + kr * WS_STRIDE + c) = v;
        }
        __syncthreads();

#pragma unroll
        for (int kk = 0; kk < BK; kk++) {
            float4 x0 = *(const float4*)(xs + kk * XS_STRIDE + ty * 8);
            float4 x1 = *(const float4*)(xs + kk * XS_STRIDE + ty * 8 + 4);
            const unsigned long long* wq =
                (const unsigned long long*)(ws + kk * WS_STRIDE + tx * 8);
            unsigned long long w0 = wq[0], w1 = wq[1], w2 = wq[2], w3 = wq[3];
            float xr[8] = {x0.x, x0.y, x0.z, x0.w, x1.x, x1.y, x1.z, x1.w};
#pragma unroll
            for (int i = 0; i < 8; i++) {
                unsigned long long xp = pack_f32x2(xr[i], xr[i]);
                asm("fma.rn.f32x2 %0, %1, %2, %0;" : "+l"(acc[i][0]) : "l"(xp), "l"(w0));
                asm("fma.rn.f32x2 %0, %1, %2, %0;" : "+l"(acc[i][1]) : "l"(xp), "l"(w1));
                asm("fma.rn.f32x2 %0, %1, %2, %0;" : "+l"(acc[i][2]) : "l"(xp), "l"(w2));
                asm("fma.rn.f32x2 %0, %1, %2, %0;" : "+l"(acc[i][3]) : "l"(xp), "l"(w3));
            }
        }
        __syncthreads();
    }

#pragma unroll
    for (int i = 0; i < 8; i++) {
        int m = mBase + ty * 8 + i;
        if (m < N_NODES) {
            float a0, a1, a2, a3, a4, a5, a6, a7;
            unpack_f32x2(a0, a1, acc[i][0]);
            unpack_f32x2(a2, a3, acc[i][1]);
            unpack_f32x2(a4, a5, acc[i][2]);
            unpack_f32x2(a6, a7, acc[i][3]);
            __nv_bfloat162 b0 = __floats2bfloat162_rn(a0, a1);
            __nv_bfloat162 b1 = __floats2bfloat162_rn(a2, a3);
            __nv_bfloat162 b2 = __floats2bfloat162_rn(a4, a5);
            __nv_bfloat162 b3 = __floats2bfloat162_rn(a6, a7);
            uint4 pack;
            pack.x = *(unsigned*)&b0; pack.y = *(unsigned*)&b1;
            pack.z = *(unsigned*)&b2; pack.w = *(unsigned*)&b3;
            *(uint4*)(g_hb + (size_t)m * HIDDEN + nBase + tx * 8) = pack;
        }
    }
}

// ---------------- K: per-node attention logits (bf16 h) -----------------------------
__global__ __launch_bounds__(256) void k_att(const float* __restrict__ att_src,
                                             const float* __restrict__ att_dst) {
    int idx = blockIdx.x * 256 + threadIdx.x;
    if (idx >= N_NODES * HEADS) return;
    int n = idx >> 3, hd = idx & 7;
    const __nv_bfloat162* hp = (const __nv_bfloat162*)(g_hb + (size_t)n * HIDDEN + hd * CDIM);
    const float* ap = att_src + hd * CDIM;
    const float* bp = att_dst + hd * CDIM;
    float ss = 0.f, sd = 0.f;
#pragma unroll
    for (int i = 0; i < 16; i++) {
        float2 hv = __bfloat1622float2(hp[i]);
        ss += hv.x * ap[2 * i] + hv.y * ap[2 * i + 1];
        sd += hv.x * bp[2 * i] + hv.y * bp[2 * i + 1];
    }
    g_asrc[idx] = ss;
    g_adst[idx] = sd;
}

// ---------------- K: warp-per-node aggregation (simple loop, LDG.128/edge) ----------
// Lane owns cols [8*lane, 8*lane+8); all 8 cols in head lane>>2.
#define AGGR_BLOCKS 1184
__global__ __launch_bounds__(256) void k_aggr(const float* __restrict__ bias) {
    const int lane   = threadIdx.x & 31;
    const int warpId = threadIdx.x >> 5;
    const int gw     = blockIdx.x * 8 + warpId;
    const int nWarps = AGGR_BLOCKS * 8;
    const int headC  = lane >> 2;          // head of this lane's 8 columns

    float bl[8], pool[8];
#pragma unroll
    for (int c = 0; c < 8; c++) {
        bl[c] = bias[8 * lane + c];
        pool[c] = 0.f;
    }

    for (int n = gw; n < N_NODES; n += nWarps) {
        const int beg = g_ptr[n];
        const int end = g_ptr[n + 1];
        const float adst = (lane < 8) ? g_adst[n * 8 + lane] : 0.f;

        float acc[8];
#pragma unroll
        for (int c = 0; c < 8; c++) acc[c] = 0.f;
        float tsum = 0.f;   // lanes 0..7 hold per-head exp-sums

        for (int base = beg; base < end; base += 32) {
            const int cnt = min(32, end - base);
            int sv = (base + lane < end) ? g_csr_src[base + lane] : 0;
            for (int e = 0; e < cnt; e++) {
                const int s = __shfl_sync(FULLM, sv, e);
                float tv = 0.f;
                if (lane < 8) {
                    float v = g_asrc[s * 8 + lane] + adst;
                    v = (v > 0.f) ? v : NEG_SLOPE * v;
                    tv = __expf(v);
                    tsum += tv;
                }
                const float aj = __shfl_sync(FULLM, tv, headC);
                uint4 hv = *(const uint4*)(g_hb + (size_t)s * HIDDEN + lane * 8);
#pragma unroll
                for (int jp = 0; jp < 4; jp++) {
                    unsigned u  = (&hv.x)[jp];
                    float lo = __uint_as_float(u << 16);
                    float hi = __uint_as_float(u & 0xFFFF0000u);
                    acc[2 * jp]     = fmaf(aj, lo, acc[2 * jp]);
                    acc[2 * jp + 1] = fmaf(aj, hi, acc[2 * jp + 1]);
                }
            }
        }
        const float denom = __shfl_sync(FULLM, tsum, headC);
        const float inv = 1.0f / (denom + 1e-16f);
#pragma unroll
        for (int c = 0; c < 8; c++) {
            float o = fmaf(acc[c], inv, bl[c]);
            o = (o > 0.f) ? o : (__expf(o) - 1.0f);
            pool[c] += o;
        }
    }
    red_add_v4(g_pooled + 8 * lane,     pool[0], pool[1], pool[2], pool[3]);
    red_add_v4(g_pooled + 8 * lane + 4, pool[4], pool[5], pool[6], pool[7]);
}

// ---------------- K: MLP head (self-restores g_pooled to 0) -------------------------
__global__ __launch_bounds__(256) void k_mlp(const float* __restrict__ W1,
                                             const float* __restrict__ b1,
                                             const float* __restrict__ W2,
                                             const float* __restrict__ b2,
                                             float* __restrict__ out) {
    __shared__ float pm[HIDDEN];
    __shared__ float z[HIDDEN / 2];
    int t = threadIdx.x;
    pm[t] = g_pooled[t] * (1.0f / (float)N_NODES);
    g_pooled[t] = 0.f;    // restore invariant for next replay
    __syncthreads();
    if (t < HIDDEN / 2) {
        float s = b1[t];
#pragma unroll 8
        for (int k = 0; k < HIDDEN; k++) s = fmaf(pm[k], W1[k * (HIDDEN / 2) + t], s);
        z[t] = fmaxf(s, 0.f);
    }
    __syncthreads();
    if (t < 6) {
        float s = b2[t];
#pragma unroll 8
        for (int j = 0; j < HIDDEN / 2; j++) s = fmaf(z[j], W2[j * 6 + t], s);
        out[t] = s;
    }
}

// ---------------- launch -----------------------------------------------------------
extern "C" void kernel_launch(void* const* d_in, const int* in_sizes, int n_in,
                              void* d_out, int out_size) {
    const float* x       = (const float*)d_in[0];
    const int*   ei      = (const int*)  d_in[1];
    const float* W       = (const float*)d_in[2];
    const float* att_src = (const float*)d_in[3];
    const float* att_dst = (const float*)d_in[4];
    const float* bias    = (const float*)d_in[5];
    const float* W1      = (const float*)d_in[6];
    const float* b1      = (const float*)d_in[7];
    const float* W2      = (const float*)d_in[8];
    const float* b2      = (const float*)d_in[9];
    float* out = (float*)d_out;

    k_hist<<<(E_TOT + 255) / 256, 256>>>(ei);       // 1
    k_scan1<<<50, 1024>>>();                        // 2
    k_scan2<<<1, 64>>>();                           // 3

    dim3 g1((N_NODES + BM - 1) / BM, HIDDEN / BN);
    k_gemm<<<g1, 256>>>(x, W);                      // 4  <- profiled slot

    k_scan3<<<50, 1024>>>();                        // 5
    k_scatter<<<(E_TOT + 255) / 256, 256>>>(ei);    // 6

    k_att<<<(N_NODES * HEADS + 255) / 256, 256>>>(att_src, att_dst);  // 7

    k_aggr<<<AGGR_BLOCKS, 256>>>(bias);             // 8

    k_mlp<<<1, 256>>>(W1, b1, W2, b2, out);         // 9
}

// round 7
// speedup vs baseline: 1.2634x; 1.0046x over previous
#include <cuda_runtime.h>
#include <cuda_bf16.h>
#include <math.h>

#define N_NODES   50000
#define N_EDGES   800000
#define E_TOT     (N_EDGES + N_NODES)
#define D_IN      128
#define HEADS     8
#define CDIM      32
#define HIDDEN    256
#define NEG_SLOPE 0.2f
#define FULLM     0xffffffffu

// ---------------- device scratch (zero-initialized at module load) ------------------
__device__ __align__(128) __nv_bfloat16 g_hb[N_NODES * HIDDEN];  // 25.6 MB
__device__ __align__(128) float g_asrc [N_NODES * HEADS];
__device__ __align__(128) float g_adst [N_NODES * HEADS];
__device__ __align__(128) float g_alpha[(size_t)E_TOT * HEADS];  // 27.2 MB CSR-aligned exps
__device__ __align__(128) float g_pooled[HIDDEN];        // zeroed by k_mlp after read
__device__ __align__(128) int   g_hist [N_NODES];        // zeroed by k_scan1 after read
__device__ __align__(128) int   g_ptr  [N_NODES + 1];
__device__ __align__(128) int   g_cur  [N_NODES];
__device__ __align__(128) int   g_csr_src[E_TOT];
__device__ __align__(128) int   g_bsum [64];
__device__ __align__(128) int   g_bofs [64];

__device__ __forceinline__ void red_add_v4(float* addr, float a, float b, float c, float d) {
    asm volatile("red.global.add.v4.f32 [%0], {%1,%2,%3,%4};"
                 :: "l"(addr), "f"(a), "f"(b), "f"(c), "f"(d) : "memory");
}
__device__ __forceinline__ unsigned long long pack_f32x2(float lo, float hi) {
    unsigned long long r;
    asm("mov.b64 %0, {%1,%2};" : "=l"(r) : "f"(lo), "f"(hi));
    return r;
}
__device__ __forceinline__ void unpack_f32x2(float& lo, float& hi, unsigned long long v) {
    asm("mov.b64 {%0,%1}, %2;" : "=f"(lo), "=f"(hi) : "l"(v));
}
__device__ __forceinline__ float leaky_exp(float v) {
    return __expf(v > 0.f ? v : NEG_SLOPE * v);
}

// ---------------- K: in-degree histogram --------------------------------------------
__global__ __launch_bounds__(256) void k_hist(const int* __restrict__ ei) {
    int e = blockIdx.x * 256 + threadIdx.x;
    if (e >= E_TOT) return;
    int d = (e < N_EDGES) ? ei[N_EDGES + e] : (e - N_EDGES);
    atomicAdd(&g_hist[d], 1);
}

// ---------------- K: scan stage 1 — 50 blocks, block-local exclusive scan -----------
#define NODES_PER_BLK 1000
__global__ __launch_bounds__(1024) void k_scan1() {
    __shared__ int sm[1024];
    const int t = threadIdx.x;
    const int b = blockIdx.x;
    const int idx = b * NODES_PER_BLK + t;
    int c = 0;
    if (t < NODES_PER_BLK) {
        c = g_hist[idx];
        g_hist[idx] = 0;           // restore invariant for next replay
    }
    sm[t] = c;
    __syncthreads();
    for (int ofs = 1; ofs < 1024; ofs <<= 1) {
        int v = (t >= ofs) ? sm[t - ofs] : 0;
        __syncthreads();
        sm[t] += v;
        __syncthreads();
    }
    if (t < NODES_PER_BLK) g_ptr[idx] = sm[t] - c;   // block-local exclusive
    if (t == 1023) g_bsum[b] = sm[1023];
}

// ---------------- K: scan stage 2 — scan the 50 block sums --------------------------
__global__ __launch_bounds__(64) void k_scan2() {
    __shared__ int sm[64];
    const int t = threadIdx.x;
    int c = (t < 50) ? g_bsum[t] : 0;
    sm[t] = c;
    __syncthreads();
    for (int ofs = 1; ofs < 64; ofs <<= 1) {
        int v = (t >= ofs) ? sm[t - ofs] : 0;
        __syncthreads();
        sm[t] += v;
        __syncthreads();
    }
    if (t < 50) g_bofs[t] = sm[t] - c;
    if (t == 0) g_ptr[N_NODES] = E_TOT;
}

// ---------------- K: scan stage 3 — apply block offsets -----------------------------
__global__ __launch_bounds__(1024) void k_scan3() {
    const int t = threadIdx.x;
    const int b = blockIdx.x;
    if (t >= NODES_PER_BLK) return;
    const int idx = b * NODES_PER_BLK + t;
    int v = g_ptr[idx] + g_bofs[b];
    g_ptr[idx] = v;
    g_cur[idx] = v;
}

// ---------------- K: scatter edges into CSR + compute softmax numerators ------------
__global__ __launch_bounds__(256) void k_scatter(const int* __restrict__ ei) {
    int e = blockIdx.x * 256 + threadIdx.x;
    if (e >= E_TOT) return;
    int s, d;
    if (e < N_EDGES) { s = ei[e]; d = ei[N_EDGES + e]; }
    else             { s = d = e - N_EDGES; }
    int pos = atomicAdd(&g_cur[d], 1);
    g_csr_src[pos] = s;
    // alpha numerators for all 8 heads (asrc/adst are 1.6MB each -> cache-hit gathers)
    float4 as0 = *(const float4*)(g_asrc + s * 8);
    float4 as1 = *(const float4*)(g_asrc + s * 8 + 4);
    float4 ad0 = *(const float4*)(g_adst + d * 8);
    float4 ad1 = *(const float4*)(g_adst + d * 8 + 4);
    float4 e0, e1;
    e0.x = leaky_exp(as0.x + ad0.x); e0.y = leaky_exp(as0.y + ad0.y);
    e0.z = leaky_exp(as0.z + ad0.z); e0.w = leaky_exp(as0.w + ad0.w);
    e1.x = leaky_exp(as1.x + ad1.x); e1.y = leaky_exp(as1.y + ad1.y);
    e1.z = leaky_exp(as1.z + ad1.z); e1.w = leaky_exp(as1.w + ad1.w);
    *(float4*)(g_alpha + (size_t)pos * 8)     = e0;
    *(float4*)(g_alpha + (size_t)pos * 8 + 4) = e1;
}

// ---------------- K: h = x @ W  (f32x2 packed FMA, 128x128 tile, 8x8 micro) ---------
#define BM 128
#define BN 128
#define BK 16
#define XS_STRIDE 132
#define WS_STRIDE 132

__global__ __launch_bounds__(256) void k_gemm(const float* __restrict__ x,
                                              const float* __restrict__ W) {
    __shared__ __align__(16) float xs[BK * XS_STRIDE];  // [k][m]
    __shared__ __align__(16) float ws[BK * WS_STRIDE];  // [k][n]
    const int t     = threadIdx.x;
    const int mBase = blockIdx.x * BM;
    const int nBase = blockIdx.y * BN;
    const int tx    = t & 15;   // 8 cols each
    const int ty    = t >> 4;   // 8 rows each

    unsigned long long acc[8][4];   // col pairs
#pragma unroll
    for (int i = 0; i < 8; i++)
#pragma unroll
        for (int j = 0; j < 4; j++) acc[i][j] = 0ull;

    for (int kBase = 0; kBase < D_IN; kBase += BK) {
#pragma unroll
        for (int p = 0; p < 2; p++) {
            int id   = t + p * 256;
            int row  = id >> 2;
            int quad = id & 3;
            int m    = mBase + row;
            float4 v = make_float4(0.f, 0.f, 0.f, 0.f);
            if (m < N_NODES)
                v = *(const float4*)(x + (size_t)m * D_IN + kBase + quad * 4);
            int k = quad * 4;
            xs[(k + 0) * XS_STRIDE + row] = v.x;
            xs[(k + 1) * XS_STRIDE + row] = v.y;
            xs[(k + 2) * XS_STRIDE + row] = v.z;
            xs[(k + 3) * XS_STRIDE + row] = v.w;
        }
#pragma unroll
        for (int p = 0; p < 2; p++) {
            int id = t + p * 256;
            int kr = id >> 5;
            int c  = (id & 31) * 4;
            float4 v = *(const float4*)(W + (size_t)(kBase + kr) * HIDDEN + nBase + c);
            *(float4*)(ws + kr * WS_STRIDE + c) = v;
        }
        __syncthreads();

#pragma unroll
        for (int kk = 0; kk < BK; kk++) {
            float4 x0 = *(const float4*)(xs + kk * XS_STRIDE + ty * 8);
            float4 x1 = *(const float4*)(xs + kk * XS_STRIDE + ty * 8 + 4);
            const unsigned long long* wq =
                (const unsigned long long*)(ws + kk * WS_STRIDE + tx * 8);
            unsigned long long w0 = wq[0], w1 = wq[1], w2 = wq[2], w3 = wq[3];
            float xr[8] = {x0.x, x0.y, x0.z, x0.w, x1.x, x1.y, x1.z, x1.w};
#pragma unroll
            for (int i = 0; i < 8; i++) {
                unsigned long long xp = pack_f32x2(xr[i], xr[i]);
                asm("fma.rn.f32x2 %0, %1, %2, %0;" : "+l"(acc[i][0]) : "l"(xp), "l"(w0));
                asm("fma.rn.f32x2 %0, %1, %2, %0;" : "+l"(acc[i][1]) : "l"(xp), "l"(w1));
                asm("fma.rn.f32x2 %0, %1, %2, %0;" : "+l"(acc[i][2]) : "l"(xp), "l"(w2));
                asm("fma.rn.f32x2 %0, %1, %2, %0;" : "+l"(acc[i][3]) : "l"(xp), "l"(w3));
            }
        }
        __syncthreads();
    }

#pragma unroll
    for (int i = 0; i < 8; i++) {
        int m = mBase + ty * 8 + i;
        if (m < N_NODES) {
            float a0, a1, a2, a3, a4, a5, a6, a7;
            unpack_f32x2(a0, a1, acc[i][0]);
            unpack_f32x2(a2, a3, acc[i][1]);
            unpack_f32x2(a4, a5, acc[i][2]);
            unpack_f32x2(a6, a7, acc[i][3]);
            __nv_bfloat162 b0 = __floats2bfloat162_rn(a0, a1);
            __nv_bfloat162 b1 = __floats2bfloat162_rn(a2, a3);
            __nv_bfloat162 b2 = __floats2bfloat162_rn(a4, a5);
            __nv_bfloat162 b3 = __floats2bfloat162_rn(a6, a7);
            uint4 pack;
            pack.x = *(unsigned*)&b0; pack.y = *(unsigned*)&b1;
            pack.z = *(unsigned*)&b2; pack.w = *(unsigned*)&b3;
            *(uint4*)(g_hb + (size_t)m * HIDDEN + nBase + tx * 8) = pack;
        }
    }
}

// ---------------- K: per-node attention logits (bf16 h) -----------------------------
__global__ __launch_bounds__(256) void k_att(const float* __restrict__ att_src,
                                             const float* __restrict__ att_dst) {
    int idx = blockIdx.x * 256 + threadIdx.x;
    if (idx >= N_NODES * HEADS) return;
    int n = idx >> 3, hd = idx & 7;
    const __nv_bfloat162* hp = (const __nv_bfloat162*)(g_hb + (size_t)n * HIDDEN + hd * CDIM);
    const float* ap = att_src + hd * CDIM;
    const float* bp = att_dst + hd * CDIM;
    float ss = 0.f, sd = 0.f;
#pragma unroll
    for (int i = 0; i < 16; i++) {
        float2 hv = __bfloat1622float2(hp[i]);
        ss += hv.x * ap[2 * i] + hv.y * ap[2 * i + 1];
        sd += hv.x * bp[2 * i] + hv.y * bp[2 * i + 1];
    }
    g_asrc[idx] = ss;
    g_adst[idx] = sd;
}

// ---------------- K: warp-per-node aggregation, 4 edges in flight -------------------
// Lane owns cols [8*lane, 8*lane+8); head of those cols = lane>>2.
#define AGGR_BLOCKS 1184
#define FMA8(aw, hv)                                                  \
    do {                                                              \
        _Pragma("unroll")                                             \
        for (int jp = 0; jp < 4; jp++) {                              \
            unsigned u  = (&(hv).x)[jp];                              \
            float lo = __uint_as_float(u << 16);                      \
            float hi = __uint_as_float(u & 0xFFFF0000u);              \
            acc[2 * jp]     = fmaf((aw), lo, acc[2 * jp]);            \
            acc[2 * jp + 1] = fmaf((aw), hi, acc[2 * jp + 1]);        \
        }                                                             \
    } while (0)

__global__ __launch_bounds__(256) void k_aggr(const float* __restrict__ bias) {
    const int lane   = threadIdx.x & 31;
    const int warpId = threadIdx.x >> 5;
    const int gw     = blockIdx.x * 8 + warpId;
    const int nWarps = AGGR_BLOCKS * 8;
    const int headC  = lane >> 2;

    float bl[8], pool[8];
#pragma unroll
    for (int c = 0; c < 8; c++) {
        bl[c] = bias[8 * lane + c];
        pool[c] = 0.f;
    }

    for (int n = gw; n < N_NODES; n += nWarps) {
        const int beg = g_ptr[n];
        const int end = g_ptr[n + 1];

        float acc[8];
#pragma unroll
        for (int c = 0; c < 8; c++) acc[c] = 0.f;
        float tsum = 0.f;   // every lane sums its own head's alphas -> local denom

        for (int base = beg; base < end; base += 32) {
            const int cnt = min(32, end - base);
            int sv = (base + lane < end) ? g_csr_src[base + lane] : 0;
            for (int g4 = 0; g4 < cnt; g4 += 4) {
                // 4 independent edges in flight
                const int s0 = __shfl_sync(FULLM, sv, g4 + 0);
                const int s1 = __shfl_sync(FULLM, sv, g4 + 1);
                const int s2 = __shfl_sync(FULLM, sv, g4 + 2);
                const int s3 = __shfl_sync(FULLM, sv, g4 + 3);
                const float a0 = g_alpha[(size_t)(base + g4) * 8 + headC];
                const float a1 = (g4 + 1 < cnt) ? g_alpha[(size_t)(base + g4 + 1) * 8 + headC] : 0.f;
                const float a2 = (g4 + 2 < cnt) ? g_alpha[(size_t)(base + g4 + 2) * 8 + headC] : 0.f;
                const float a3 = (g4 + 3 < cnt) ? g_alpha[(size_t)(base + g4 + 3) * 8 + headC] : 0.f;
                uint4 h0 = *(const uint4*)(g_hb + (size_t)s0 * HIDDEN + lane * 8);
                uint4 h1 = *(const uint4*)(g_hb + (size_t)s1 * HIDDEN + lane * 8);
                uint4 h2 = *(const uint4*)(g_hb + (size_t)s2 * HIDDEN + lane * 8);
                uint4 h3 = *(const uint4*)(g_hb + (size_t)s3 * HIDDEN + lane * 8);
                tsum += (a0 + a1) + (a2 + a3);
                FMA8(a0, h0);
                FMA8(a1, h1);
                FMA8(a2, h2);
                FMA8(a3, h3);
            }
        }
        const float inv = 1.0f / (tsum + 1e-16f);
#pragma unroll
        for (int c = 0; c < 8; c++) {
            float o = fmaf(acc[c], inv, bl[c]);
            o = (o > 0.f) ? o : (__expf(o) - 1.0f);
            pool[c] += o;
        }
    }
    red_add_v4(g_pooled + 8 * lane,     pool[0], pool[1], pool[2], pool[3]);
    red_add_v4(g_pooled + 8 * lane + 4, pool[4], pool[5], pool[6], pool[7]);
}

// ---------------- K: MLP head (self-restores g_pooled to 0) -------------------------
__global__ __launch_bounds__(256) void k_mlp(const float* __restrict__ W1,
                                             const float* __restrict__ b1,
                                             const float* __restrict__ W2,
                                             const float* __restrict__ b2,
                                             float* __restrict__ out) {
    __shared__ float pm[HIDDEN];
    __shared__ float z[HIDDEN / 2];
    int t = threadIdx.x;
    pm[t] = g_pooled[t] * (1.0f / (float)N_NODES);
    g_pooled[t] = 0.f;    // restore invariant for next replay
    __syncthreads();
    if (t < HIDDEN / 2) {
        float s = b1[t];
#pragma unroll 8
        for (int k = 0; k < HIDDEN; k++) s = fmaf(pm[k], W1[k * (HIDDEN / 2) + t], s);
        z[t] = fmaxf(s, 0.f);
    }
    __syncthreads();
    if (t < 6) {
        float s = b2[t];
#pragma unroll 8
        for (int j = 0; j < HIDDEN / 2; j++) s = fmaf(z[j], W2[j * 6 + t], s);
        out[t] = s;
    }
}

// ---------------- launch -----------------------------------------------------------
extern "C" void kernel_launch(void* const* d_in, const int* in_sizes, int n_in,
                              void* d_out, int out_size) {
    const float* x       = (const float*)d_in[0];
    const int*   ei      = (const int*)  d_in[1];
    const float* W       = (const float*)d_in[2];
    const float* att_src = (const float*)d_in[3];
    const float* att_dst = (const float*)d_in[4];
    const float* bias    = (const float*)d_in[5];
    const float* W1      = (const float*)d_in[6];
    const float* b1      = (const float*)d_in[7];
    const float* W2      = (const float*)d_in[8];
    const float* b2      = (const float*)d_in[9];
    float* out = (float*)d_out;

    k_hist<<<(E_TOT + 255) / 256, 256>>>(ei);       // 1
    k_scan1<<<50, 1024>>>();                        // 2
    k_scan2<<<1, 64>>>();                           // 3

    dim3 g1((N_NODES + BM - 1) / BM, HIDDEN / BN);
    k_gemm<<<g1, 256>>>(x, W);                      // 4  <- profiled slot

    k_scan3<<<50, 1024>>>();                        // 5
    k_att<<<(N_NODES * HEADS + 255) / 256, 256>>>(att_src, att_dst);  // 6
    k_scatter<<<(E_TOT + 255) / 256, 256>>>(ei);    // 7 (needs att + scan3)

    k_aggr<<<AGGR_BLOCKS, 256>>>(bias);             // 8

    k_mlp<<<1, 256>>>(W1, b1, W2, b2, out);         // 9
}